// round 4
// baseline (speedup 1.0000x reference)
#include <cuda_runtime.h>

// UnarySqrt recurrence, unipolar, jk_trace=True.
// On exact {0.0f, 1.0f} IEEE patterns (0x00000000 / 0x3F800000):
//   out    = trace | x     ( == (1-trace)*x + trace )
//   trace' = x & ~trace    ( == out * (1-trace) )
// Bit-exact vs the float reference (verified rel_err=0.0 in R3).
//
// R4: time-tiled bursts. 2 column streams/thread (i, i+half), chunk of 4
// t-steps per stream per iteration -> 8 back-to-back 16B loads, then compute,
// then 8 back-to-back 16B stores. Longer same-direction DRAM runs + MLP=8.
// Geometry: 256 thr x 512 CTAs = exactly 4 CTAs/SM, one balanced wave.

#define T_STEPS 64
#define CH 4

__global__ __launch_bounds__(256)
void unary_sqrt_kernel(const uint4* __restrict__ bits,
                       const uint4* __restrict__ trace0,
                       uint4* __restrict__ out,
                       int nvec, int half)
{
    int i = blockIdx.x * blockDim.x + threadIdx.x;
    if (i >= half) return;
    int j = i + half;

    uint4 ta = __ldcs(&trace0[i]);
    uint4 tb = __ldcs(&trace0[j]);

    for (int tbase = 0; tbase < T_STEPS; tbase += CH) {
        uint4 xa[CH], xb[CH];

        // burst: 2*CH address-independent 16B loads
        #pragma unroll
        for (int k = 0; k < CH; ++k) {
            const size_t base = (size_t)(tbase + k) * nvec;
            xa[k] = __ldcs(&bits[base + i]);
            xb[k] = __ldcs(&bits[base + j]);
        }

        // recurrence (in-place: x[k] becomes out[k])
        #pragma unroll
        for (int k = 0; k < CH; ++k) {
            uint4 oa, ob;
            oa.x = xa[k].x | ta.x;  oa.y = xa[k].y | ta.y;
            oa.z = xa[k].z | ta.z;  oa.w = xa[k].w | ta.w;
            ob.x = xb[k].x | tb.x;  ob.y = xb[k].y | tb.y;
            ob.z = xb[k].z | tb.z;  ob.w = xb[k].w | tb.w;

            ta.x = xa[k].x & ~ta.x;  ta.y = xa[k].y & ~ta.y;
            ta.z = xa[k].z & ~ta.z;  ta.w = xa[k].w & ~ta.w;
            tb.x = xb[k].x & ~tb.x;  tb.y = xb[k].y & ~tb.y;
            tb.z = xb[k].z & ~tb.z;  tb.w = xb[k].w & ~tb.w;

            xa[k] = oa;  xb[k] = ob;
        }

        // burst: 2*CH back-to-back 16B stores
        #pragma unroll
        for (int k = 0; k < CH; ++k) {
            const size_t base = (size_t)(tbase + k) * nvec;
            __stcs(&out[base + i], xa[k]);
            __stcs(&out[base + j], xb[k]);
        }
    }
}

extern "C" void kernel_launch(void* const* d_in, const int* in_sizes, int n_in,
                              void* d_out, int out_size)
{
    // metadata order: input [T, N] float32, trace0 [N] float32
    const uint4* bits   = (const uint4*)d_in[0];
    const uint4* trace0 = (const uint4*)d_in[1];
    uint4*       out    = (uint4*)d_out;

    int N    = in_sizes[1];   // 1048576
    int nvec = N / 4;         // 262144 uint4 vectors
    int half = nvec / 2;      // 131072

    int threads = 256;
    int blocks  = (half + threads - 1) / threads;  // 512 -> 4 CTAs/SM, 1 wave
    unary_sqrt_kernel<<<blocks, threads>>>(bits, trace0, out, nvec, half);
}